// round 10
// baseline (speedup 1.0000x reference)
#include <cuda_runtime.h>
#include <math.h>

// Problem constants (fixed by setup_inputs)
#define BB 8
#define NN 1024
#define NTOK (BB*NN)   // 8192
#define HH 8
#define SCALE 0.2236067977499790f  // 1/sqrt(20)

// ---------------------------------------------------------------------------
// Compile-time blade tables.
// idx: 0:(),1:(0),2:(1),3:(2),4:(3),5:(01),6:(02),7:(03),8:(12),9:(13),10:(23),
//      11:(012),12:(013),13:(023),14:(123),15:(0123)
// ---------------------------------------------------------------------------
constexpr int BL_GRADE[16]= {0,1,1,1,1,2,2,2,2,2,2,3,3,3,3,4};
constexpr int BL_PART[16] = {1,0,5,6,7,2,3,4,11,12,13,8,9,10,15,14}; // blade^e0
constexpr unsigned INNER_M = 0x471Du;   // 1 if e0 not in blade
constexpr unsigned HAS0_M  = 0xB8E2u;   // 1 if e0 in blade
// Inner blades (INNER=1), ascending: {0,2,3,4,8,9,10,14} packed as nibbles
constexpr unsigned IB_P = 0xEA984320u;

constexpr unsigned long long pack4(const int (&t)[16]) {
    unsigned long long v = 0;
    for (int i = 0; i < 16; i++) v |= (unsigned long long)t[i] << (4*i);
    return v;
}
constexpr unsigned long long GRADE_P = pack4(BL_GRADE);
constexpr unsigned long long PART_P  = pack4(BL_PART);

__host__ __device__ constexpr int gp_sign(int i, int j) {  // sign of blade_i*blade_j, 0 if e0*e0
    const int M[16] = {0,1,2,4,8,3,5,9,6,10,12,7,11,13,14,15};
    int mi = M[i], mj = M[j];
    if (mi & mj & 1) return 0;
    int inv = 0;
    for (int y = 0; y < 4; y++)
        if ((mj >> y) & 1)
            for (int z = y+1; z < 4; z++) inv += (mi >> z) & 1;
    return (inv & 1) ? -1 : 1;
}
__host__ __device__ constexpr int gp_out(int i, int j) {
    const int M[16]   = {0,1,2,4,8,3,5,9,6,10,12,7,11,13,14,15};
    const int M2I[16] = {0,1,2,5,3,6,8,11,4,7,9,12,10,13,14,15};
    return M2I[M[i] ^ M[j]];
}

// Scratch (device globals; no allocation allowed)
__device__ float g_S_mv[NTOK*256];
__device__ float g_S_s [NTOK*32];
__device__ float g_Q_mv[NTOK*768];   // qkv mv (48 ch) / mlp hidden mv (32 ch)
__device__ float g_Q_s [NTOK*96];    // qkv s (96) / mlp hidden s (64)
__device__ float g_A_mv[NTOK*256];   // attn out mv / geo product
__device__ float g_A_s [NTOK*32];    // attn out s / gated scalars

__device__ __forceinline__ float gelu_tanh(float x) {
    float x3 = x*x*x;
    return 0.5f*x*(1.f + tanhf(0.7978845608028654f*(x + 0.044715f*x3)));
}

// ---------------------------------------------------------------------------
// Init
// ---------------------------------------------------------------------------
__device__ __forceinline__ float mv0_val(int a, float x, float y, float z) {
    if (a == 14) return 1.f;
    if (a == 13) return -x;
    if (a == 12) return y;
    if (a == 11) return -z;
    return 0.f;
}

__global__ void k_init(const float* __restrict__ inputs,
                       const float* __restrict__ win_mv,  // (16,1,9)
                       const float* __restrict__ win_bs,  // (32,)
                       float* __restrict__ Smv, float* __restrict__ Ss) {
    int wid = threadIdx.x >> 5, lane = threadIdx.x & 31;
    int tok = blockIdx.x*8 + wid;
    if (tok >= NTOK) return;
    float x = inputs[tok*3+0], y = inputs[tok*3+1], z = inputs[tok*3+2];
    int a = lane & 15;
    int g = (int)((GRADE_P >> (4*a)) & 15);
    int p = (int)((PART_P  >> (4*a)) & 15);
    int h0 = (HAS0_M >> a) & 1;
    float va = mv0_val(a,x,y,z), vp = mv0_val(p,x,y,z);
    for (int oi = lane; oi < 256; oi += 32) {
        int o = oi >> 4;
        float v = __ldg(&win_mv[o*9+g]) * va;
        if (h0) v += __ldg(&win_mv[o*9+4+g]) * vp;
        Smv[(size_t)tok*256 + oi] = v;
    }
    Ss[(size_t)tok*32 + lane] = __ldg(&win_bs[lane]);
}

// ---------------------------------------------------------------------------
// Equi-linear, fused optional LayerNorm, BASIS sparsity, x in registers.
// One warp = one token, WARPS tokens per block.
// If GEO: outputs (O=32 mv ch, SO=64 s) are kept in smem and the geometric
// product + gelu gates are applied in-warp; ymv/ys receive gp (16ch) / sh (32).
// ---------------------------------------------------------------------------
template<int WARPS, int I, int O, int SI, int SO, bool RES, bool LN, bool GEO>
__global__ __launch_bounds__(WARPS*32) void k_equi(
        const float* __restrict__ xmv, const float* __restrict__ xs,
        const float* __restrict__ wmv, const float* __restrict__ wsm,
        const float* __restrict__ wms, const float* __restrict__ wss,
        const float* __restrict__ rmv, const float* __restrict__ rs,
        float* __restrict__ ymv, float* __restrict__ ys) {
    constexpr int WF = O*I*9;
    constexpr int NT = WARPS*32;
    constexpr int HST = 17;                 // padded per-channel stride for GEO
    constexpr int HS0 = O*HST;              // scalar offset in s_h
    __shared__ float s_wk[WF];              // relaid out: [k][o][i]
    __shared__ float s_ts[WARPS][SI + I];   // raw s (SI) then x[:,0] (I)
    __shared__ float s_ex[WARPS][O];        // blade-0 scalar->mv contributions
    __shared__ float s_h[GEO ? WARPS*(O*HST + SO) : 1];
    int tid = threadIdx.x;
    for (int idx = tid; idx < WF; idx += NT) {
        int o = idx / (I*9); int r = idx - o*(I*9); int i = r / 9; int k = r - i*9;
        s_wk[(k*O + o)*I + i] = wmv[idx];
    }
    int wid = tid >> 5, lane = tid & 31;
    int tok = blockIdx.x*WARPS + wid;
    int a = lane & 15;
    int g  = (int)((GRADE_P >> (4*a)) & 15);
    int pp = (int)((PART_P  >> (4*a)) & 15);
    int h0 = (HAS0_M >> a) & 1;
    const float* xm = xmv + (size_t)tok*(I*16);
    float xa[I], xp[I];
    #pragma unroll
    for (int i = 0; i < I; i++) { xa[i] = xm[i*16 + a]; xp[i] = xm[i*16 + pp]; }
    float sv = xs[(size_t)tok*SI + lane];
    s_ts[wid][lane] = sv;
    if (lane < I) s_ts[wid][SI + lane] = xm[lane*16];
    float r1 = 1.f, r2 = 1.f;
    if (LN) {
        float innf = ((INNER_M >> a) & 1) ? 1.f : 0.f;
        float acc = 0.f;
        #pragma unroll
        for (int i = 0; i < I; i++) acc += xa[i]*xa[i];
        acc *= innf;
        #pragma unroll
        for (int ofs = 1; ofs < 16; ofs <<= 1) acc += __shfl_xor_sync(0xffffffffu, acc, ofs);
        r1 = rsqrtf(acc*(1.f/(float)I) + 1e-6f);
        float a2 = sv*sv;
        #pragma unroll
        for (int ofs = 1; ofs < 32; ofs <<= 1) a2 += __shfl_xor_sync(0xffffffffu, a2, ofs);
        r2 = rsqrtf(a2*(1.f/(float)SI) + 1e-6f);
        #pragma unroll
        for (int i = 0; i < I; i++) { xa[i] *= r1; xp[i] *= r1; }
    }
    __syncthreads();
    // blade-0 scalar->mv contributions (wsm @ s)
    for (int o = lane; o < O; o += 32) {
        const float4* w4 = reinterpret_cast<const float4*>(wsm + o*SI);
        float acc = 0.f;
        #pragma unroll
        for (int j4 = 0; j4 < SI/4; j4++) {
            float4 w = __ldg(&w4[j4]);
            acc = fmaf(w.x, s_ts[wid][j4*4+0], acc);
            acc = fmaf(w.y, s_ts[wid][j4*4+1], acc);
            acc = fmaf(w.z, s_ts[wid][j4*4+2], acc);
            acc = fmaf(w.w, s_ts[wid][j4*4+3], acc);
        }
        s_ex[wid][o] = acc * r2;
    }
    __syncwarp();
    // main mv outputs
    for (int oi = lane; oi < O*16; oi += 32) {
        int o = oi >> 4;
        const float4* w1 = reinterpret_cast<const float4*>(&s_wk[(g*O + o)*I]);
        float acc = 0.f;
        #pragma unroll
        for (int i4 = 0; i4 < I/4; i4++) {
            float4 w = w1[i4];
            acc = fmaf(w.x, xa[i4*4+0], acc);
            acc = fmaf(w.y, xa[i4*4+1], acc);
            acc = fmaf(w.z, xa[i4*4+2], acc);
            acc = fmaf(w.w, xa[i4*4+3], acc);
        }
        if (h0) {
            const float4* w2 = reinterpret_cast<const float4*>(&s_wk[((4+g)*O + o)*I]);
            #pragma unroll
            for (int i4 = 0; i4 < I/4; i4++) {
                float4 w = w2[i4];
                acc = fmaf(w.x, xp[i4*4+0], acc);
                acc = fmaf(w.y, xp[i4*4+1], acc);
                acc = fmaf(w.z, xp[i4*4+2], acc);
                acc = fmaf(w.w, xp[i4*4+3], acc);
            }
        }
        if (a == 0) acc += s_ex[wid][o];
        if (GEO) {
            s_h[wid*(O*HST+SO) + o*HST + a] = acc;
        } else {
            if (RES) acc += rmv[(size_t)tok*O*16 + oi];
            ymv[(size_t)tok*O*16 + oi] = acc;
        }
    }
    // scalar outputs
    for (int so = lane; so < SO; so += 32) {
        const float4* ws4 = reinterpret_cast<const float4*>(wss + so*SI);
        float accs = 0.f;
        #pragma unroll
        for (int j4 = 0; j4 < SI/4; j4++) {
            float4 w = __ldg(&ws4[j4]);
            accs = fmaf(w.x, s_ts[wid][j4*4+0], accs);
            accs = fmaf(w.y, s_ts[wid][j4*4+1], accs);
            accs = fmaf(w.z, s_ts[wid][j4*4+2], accs);
            accs = fmaf(w.w, s_ts[wid][j4*4+3], accs);
        }
        const float4* wm4 = reinterpret_cast<const float4*>(wms + so*I);
        float accm = 0.f;
        #pragma unroll
        for (int i4 = 0; i4 < I/4; i4++) {
            float4 w = __ldg(&wm4[i4]);
            accm = fmaf(w.x, s_ts[wid][SI + i4*4+0], accm);
            accm = fmaf(w.y, s_ts[wid][SI + i4*4+1], accm);
            accm = fmaf(w.z, s_ts[wid][SI + i4*4+2], accm);
            accm = fmaf(w.w, s_ts[wid][SI + i4*4+3], accm);
        }
        float acc = accs*r2 + accm*r1;
        if (GEO) {
            s_h[wid*(O*HST+SO) + HS0 + so] = acc;
        } else {
            if (RES) acc += rs[(size_t)tok*SO + so];
            ys[(size_t)tok*SO + so] = acc;
        }
    }
    if (GEO) {
        __syncwarp();
        const float* hw = s_h + wid*(O*HST+SO);
        if (lane < 16) {
            int ch = lane;
            float av[16], bv[16];
            #pragma unroll
            for (int k = 0; k < 16; k++) {
                av[k] = hw[ch*HST + k];
                bv[k] = hw[(ch+16)*HST + k];
            }
            float gg[16];
            #pragma unroll
            for (int k = 0; k < 16; k++) gg[k] = 0.f;
            #pragma unroll
            for (int i = 0; i < 16; i++) {
                #pragma unroll
                for (int j = 0; j < 16; j++) {
                    const int sg = gp_sign(i, j);
                    if (sg != 0) {
                        const int k = gp_out(i, j);
                        gg[k] = fmaf((sg > 0 ? av[i] : -av[i]), bv[j], gg[k]);
                    }
                }
            }
            float gate = gelu_tanh(gg[0]);
            float4* op = reinterpret_cast<float4*>(ymv + (size_t)tok*256 + ch*16);
            #pragma unroll
            for (int q = 0; q < 4; q++) {
                float4 v;
                v.x = gg[4*q+0]*gate; v.y = gg[4*q+1]*gate;
                v.z = gg[4*q+2]*gate; v.w = gg[4*q+3]*gate;
                op[q] = v;
            }
        } else {
            int j0 = (lane - 16)*2;
            #pragma unroll
            for (int r = 0; r < 2; r++) {
                int j = j0 + r;
                float x1 = hw[HS0 + j];
                float x2 = hw[HS0 + 32 + j];
                ys[(size_t)tok*32 + j] = x1 * gelu_tanh(x2);
            }
        }
    }
}

// ---------------------------------------------------------------------------
// Flash attention (fp32). Q/K compacted to the 20 effective score dims
// (8 inner blades x 2 mv channels + 4 scalars); V keeps all 36 dims.
// Score phase: 4x4 register tiles.  O-phase: 4 rows x 9 dims x 4-way key split.
// ---------------------------------------------------------------------------
#define KQ 20
#define KQP 21
#define KD 36
#define KDP 37
#define PSP 65
__global__ __launch_bounds__(256) void k_attn(
        const float* __restrict__ qkv_mv, const float* __restrict__ qkv_s,
        float* __restrict__ omv, float* __restrict__ os) {
    __shared__ float qs[64*KQP], ks[64*KQP], vs[64*KDP];
    __shared__ float ps[64*PSP];
    __shared__ float m_s[64], l_s[64], corr_s[64];
    int tid = threadIdx.x;
    int bh = blockIdx.y, b = bh >> 3, h = bh & 7;
    int qtok0 = b*NN + blockIdx.x*64;
    // load compact q
    for (int idx = tid; idx < 64*KQ; idx += 256) {
        int r = idx / KQ, d = idx - r*KQ;
        int t = qtok0 + r;
        float v;
        if (d < 16) {
            int c = d >> 3, ib = (int)((IB_P >> (4*(d & 7))) & 15);
            v = qkv_mv[(size_t)t*768 + (h*2+c)*16 + ib];
        } else v = qkv_s[(size_t)t*96 + h*4 + (d-16)];
        qs[r*KQP + d] = v;
    }
    if (tid < 64) { m_s[tid] = -1e30f; l_s[tid] = 0.f; }
    // o-phase mapping
    int rq  = tid >> 4;
    int ogl = (tid >> 2) & 3;
    int kspl= tid & 3;
    float o4[4][9];
    #pragma unroll
    for (int r = 0; r < 4; r++)
        #pragma unroll
        for (int d = 0; d < 9; d++) o4[r][d] = 0.f;
    int kl = tid & 15;   // score phase: rq rows x kl key-quads
    int ktok0 = b*NN;
    for (int kt = 0; kt < NN/64; kt++) {
        __syncthreads();
        // load compact k
        for (int idx = tid; idx < 64*KQ; idx += 256) {
            int r = idx / KQ, d = idx - r*KQ;
            int t = ktok0 + kt*64 + r;
            float v;
            if (d < 16) {
                int c = d >> 3, ib = (int)((IB_P >> (4*(d & 7))) & 15);
                v = qkv_mv[(size_t)t*768 + 256 + (h*2+c)*16 + ib];
            } else v = qkv_s[(size_t)t*96 + 32 + h*4 + (d-16)];
            ks[r*KQP + d] = v;
        }
        // load full v
        for (int idx = tid; idx < 64*KD; idx += 256) {
            int r = idx / KD, d = idx - r*KD;
            int t = ktok0 + kt*64 + r;
            float v;
            if (d < 32) { int c = d >> 4, i = d & 15;
                v = qkv_mv[(size_t)t*768 + 512 + (h*2+c)*16 + i]; }
            else v = qkv_s[(size_t)t*96 + 64 + h*4 + (d-32)];
            vs[r*KDP + d] = v;
        }
        __syncthreads();
        // ---- score phase (20 dims) ----
        float sc[4][4];
        #pragma unroll
        for (int i = 0; i < 4; i++)
            #pragma unroll
            for (int j = 0; j < 4; j++) sc[i][j] = 0.f;
        #pragma unroll 4
        for (int d = 0; d < KQ; d++) {
            float q4[4], k4[4];
            #pragma unroll
            for (int i = 0; i < 4; i++) q4[i] = qs[(rq*4+i)*KQP + d];
            #pragma unroll
            for (int j = 0; j < 4; j++) k4[j] = ks[(kl*4+j)*KQP + d];
            #pragma unroll
            for (int i = 0; i < 4; i++)
                #pragma unroll
                for (int j = 0; j < 4; j++) sc[i][j] = fmaf(q4[i], k4[j], sc[i][j]);
        }
        #pragma unroll
        for (int i = 0; i < 4; i++) {
            float tm = -1e30f;
            #pragma unroll
            for (int j = 0; j < 4; j++) { sc[i][j] *= SCALE; tm = fmaxf(tm, sc[i][j]); }
            #pragma unroll
            for (int ofs = 1; ofs < 16; ofs <<= 1)
                tm = fmaxf(tm, __shfl_xor_sync(0xffffffffu, tm, ofs));
            int row = rq*4 + i;
            float mo = m_s[row];
            float nm = fmaxf(mo, tm);
            float sum = 0.f;
            #pragma unroll
            for (int j = 0; j < 4; j++) {
                float pv = __expf(sc[i][j] - nm);
                sum += pv;
                ps[row*PSP + kl*4 + j] = pv;
            }
            #pragma unroll
            for (int ofs = 1; ofs < 16; ofs <<= 1)
                sum += __shfl_xor_sync(0xffffffffu, sum, ofs);
            if (kl == 0) {
                float corr = __expf(mo - nm);
                corr_s[row] = corr;
                m_s[row] = nm;
                l_s[row] = l_s[row]*corr + sum;
            }
        }
        __syncthreads();
        // ---- o accumulation phase ----
        float c4[4];
        #pragma unroll
        for (int r = 0; r < 4; r++) c4[r] = corr_s[rq*4 + r];
        #pragma unroll
        for (int r = 0; r < 4; r++)
            #pragma unroll
            for (int d = 0; d < 9; d++) o4[r][d] *= c4[r];
        int key0 = kspl*16;
        for (int kk = 0; kk < 16; kk++) {
            int key = key0 + kk;
            float p0 = ps[(rq*4+0)*PSP + key];
            float p1 = ps[(rq*4+1)*PSP + key];
            float p2 = ps[(rq*4+2)*PSP + key];
            float p3 = ps[(rq*4+3)*PSP + key];
            const float* vrow = &vs[key*KDP + ogl*9];
            #pragma unroll
            for (int d = 0; d < 9; d++) {
                float v = vrow[d];
                o4[0][d] = fmaf(p0, v, o4[0][d]);
                o4[1][d] = fmaf(p1, v, o4[1][d]);
                o4[2][d] = fmaf(p2, v, o4[2][d]);
                o4[3][d] = fmaf(p3, v, o4[3][d]);
            }
        }
    }
    // reduce key splits
    #pragma unroll
    for (int r = 0; r < 4; r++)
        #pragma unroll
        for (int d = 0; d < 9; d++) {
            float v = o4[r][d];
            v += __shfl_xor_sync(0xffffffffu, v, 1);
            v += __shfl_xor_sync(0xffffffffu, v, 2);
            o4[r][d] = v;
        }
    if (kspl == 0) {
        #pragma unroll
        for (int r = 0; r < 4; r++) {
            int row = rq*4 + r;
            float inv = 1.f / l_s[row];
            int t = qtok0 + row;
            #pragma unroll
            for (int dd = 0; dd < 9; dd++) {
                int d = ogl*9 + dd;
                float val = o4[r][dd]*inv;
                if (d < 32) omv[(size_t)t*256 + (h*2 + (d>>4))*16 + (d&15)] = val;
                else        os[(size_t)t*32 + h*4 + (d-32)] = val;
            }
        }
    }
}

// ---------------------------------------------------------------------------
// Final readout
// ---------------------------------------------------------------------------
__global__ void k_final(const float* __restrict__ Smv, const float* __restrict__ Ss,
                        const float* __restrict__ wout_mv, const float* __restrict__ wout_sm,
                        float* __restrict__ out) {
    __shared__ float red[256];
    int b = blockIdx.x;
    float acc = 0.f;
    for (int n = threadIdx.x; n < NN; n += 256) {
        size_t t = (size_t)b*NN + n;
        float v = 0.f;
        #pragma unroll
        for (int i = 0; i < 16; i++) v = fmaf(__ldg(&wout_mv[i*9]), Smv[t*256 + i*16], v);
        #pragma unroll
        for (int j = 0; j < 32; j++) v = fmaf(__ldg(&wout_sm[j]), Ss[t*32 + j], v);
        acc += v;
    }
    red[threadIdx.x] = acc;
    __syncthreads();
    for (int s = 128; s; s >>= 1) {
        if (threadIdx.x < s) red[threadIdx.x] += red[threadIdx.x + s];
        __syncthreads();
    }
    if (threadIdx.x == 0) out[b] = red[0] * (1.f/NN);
}

// ---------------------------------------------------------------------------
// Host
// ---------------------------------------------------------------------------
template<int WARPS, int I, int O, int SI, int SO, bool RES, bool LN, bool GEO>
static void launch_equi(const float* xmv, const float* xs,
                        const float* wmv, const float* wsm,
                        const float* wms, const float* wss,
                        const float* rmv, const float* rs,
                        float* ymv, float* ys) {
    k_equi<WARPS,I,O,SI,SO,RES,LN,GEO><<<NTOK/WARPS, WARPS*32>>>(
        xmv, xs, wmv, wsm, wms, wss, rmv, rs, ymv, ys);
}

extern "C" void kernel_launch(void* const* d_in, const int* in_sizes, int n_in,
                              void* d_out, int out_size) {
    const float* inputs    = (const float*)d_in[0];
    const float* win_mv    = (const float*)d_in[1];
    const float* win_bs    = (const float*)d_in[3];
    const float* qkv_wmv   = (const float*)d_in[4];
    const float* qkv_wsm   = (const float*)d_in[5];
    const float* qkv_wms   = (const float*)d_in[6];
    const float* qkv_wss   = (const float*)d_in[7];
    const float* out_wmv   = (const float*)d_in[8];
    const float* out_wsm   = (const float*)d_in[9];
    const float* out_wms   = (const float*)d_in[10];
    const float* out_wss   = (const float*)d_in[11];
    const float* m1_wmv    = (const float*)d_in[12];
    const float* m1_wsm    = (const float*)d_in[13];
    const float* m1_wms    = (const float*)d_in[14];
    const float* m1_wss    = (const float*)d_in[15];
    const float* m2_wmv    = (const float*)d_in[16];
    const float* m2_wsm    = (const float*)d_in[17];
    const float* m2_wms    = (const float*)d_in[18];
    const float* m2_wss    = (const float*)d_in[19];
    const float* wout_mv   = (const float*)d_in[20];
    const float* wout_sm   = (const float*)d_in[21];
    float* out = (float*)d_out;

    int L = in_sizes[4] / (48*16*9);

    float *Smv, *Ss, *Qmv, *Qs, *Amv, *As;
    cudaGetSymbolAddress((void**)&Smv, g_S_mv);
    cudaGetSymbolAddress((void**)&Ss,  g_S_s);
    cudaGetSymbolAddress((void**)&Qmv, g_Q_mv);
    cudaGetSymbolAddress((void**)&Qs,  g_Q_s);
    cudaGetSymbolAddress((void**)&Amv, g_A_mv);
    cudaGetSymbolAddress((void**)&As,  g_A_s);

    k_init<<<NTOK/8, 256>>>(inputs, win_mv, win_bs, Smv, Ss);

    for (int l = 0; l < L; l++) {
        // --- attention block (LN fused into qkv equi) ---
        launch_equi<16,16,48,32,96,false,true,false>(Smv, Ss,
            qkv_wmv + (size_t)l*48*16*9, qkv_wsm + (size_t)l*48*32,
            qkv_wms + (size_t)l*96*16,   qkv_wss + (size_t)l*96*32,
            nullptr, nullptr, Qmv, Qs);
        k_attn<<<dim3(NN/64, BB*HH), 256>>>(Qmv, Qs, Amv, As);
        launch_equi<16,16,16,32,32,true,false,false>(Amv, As,
            out_wmv + (size_t)l*16*16*9, out_wsm + (size_t)l*16*32,
            out_wms + (size_t)l*32*16,   out_wss + (size_t)l*32*32,
            Smv, Ss, Smv, Ss);
        // --- mlp block: LN + equi + geometric product + gates in ONE kernel ---
        launch_equi<8,16,32,32,64,false,true,true>(Smv, Ss,
            m1_wmv + (size_t)l*32*16*9, m1_wsm + (size_t)l*32*32,
            m1_wms + (size_t)l*64*16,   m1_wss + (size_t)l*64*32,
            nullptr, nullptr, Amv, As);
        launch_equi<16,16,16,32,32,true,false,false>(Amv, As,
            m2_wmv + (size_t)l*16*16*9, m2_wsm + (size_t)l*16*32,
            m2_wms + (size_t)l*32*16,   m2_wss + (size_t)l*32*32,
            Smv, Ss, Smv, Ss);
    }

    k_final<<<BB, 256>>>(Smv, Ss, wout_mv, wout_sm, out);
}

// round 11
// speedup vs baseline: 1.6451x; 1.6451x over previous
#include <cuda_runtime.h>
#include <math.h>

// Problem constants (fixed by setup_inputs)
#define BB 8
#define NN 1024
#define NTOK (BB*NN)   // 8192
#define HH 8
#define SCALE 0.2236067977499790f  // 1/sqrt(20)

// ---------------------------------------------------------------------------
// Compile-time blade tables.
// idx: 0:(),1:(0),2:(1),3:(2),4:(3),5:(01),6:(02),7:(03),8:(12),9:(13),10:(23),
//      11:(012),12:(013),13:(023),14:(123),15:(0123)
// ---------------------------------------------------------------------------
constexpr int BL_GRADE[16]= {0,1,1,1,1,2,2,2,2,2,2,3,3,3,3,4};
constexpr int BL_PART[16] = {1,0,5,6,7,2,3,4,11,12,13,8,9,10,15,14}; // blade^e0
constexpr unsigned INNER_M = 0x471Du;   // 1 if e0 not in blade
constexpr unsigned HAS0_M  = 0xB8E2u;   // 1 if e0 in blade
// Inner blades (INNER=1), ascending: {0,2,3,4,8,9,10,14} packed as nibbles
constexpr unsigned IB_P = 0xEA984320u;

constexpr unsigned long long pack4(const int (&t)[16]) {
    unsigned long long v = 0;
    for (int i = 0; i < 16; i++) v |= (unsigned long long)t[i] << (4*i);
    return v;
}
constexpr unsigned long long GRADE_P = pack4(BL_GRADE);
constexpr unsigned long long PART_P  = pack4(BL_PART);

__host__ __device__ constexpr int gp_sign(int i, int j) {  // sign of blade_i*blade_j, 0 if e0*e0
    const int M[16] = {0,1,2,4,8,3,5,9,6,10,12,7,11,13,14,15};
    int mi = M[i], mj = M[j];
    if (mi & mj & 1) return 0;
    int inv = 0;
    for (int y = 0; y < 4; y++)
        if ((mj >> y) & 1)
            for (int z = y+1; z < 4; z++) inv += (mi >> z) & 1;
    return (inv & 1) ? -1 : 1;
}
__host__ __device__ constexpr int gp_out(int i, int j) {
    const int M[16]   = {0,1,2,4,8,3,5,9,6,10,12,7,11,13,14,15};
    const int M2I[16] = {0,1,2,5,3,6,8,11,4,7,9,12,10,13,14,15};
    return M2I[M[i] ^ M[j]];
}

// Scratch (device globals; no allocation allowed)
__device__ float g_S_mv[NTOK*256];
__device__ float g_S_s [NTOK*32];
__device__ float g_Q_mv[NTOK*768];   // qkv mv (48 ch) / mlp hidden mv (32 ch)
__device__ float g_Q_s [NTOK*96];    // qkv s (96) / mlp hidden s (64)
__device__ float g_A_mv[NTOK*256];   // attn out mv / geo product
__device__ float g_A_s [NTOK*32];    // attn out s / gated scalars

__device__ __forceinline__ float gelu_tanh(float x) {
    float x3 = x*x*x;
    return 0.5f*x*(1.f + tanhf(0.7978845608028654f*(x + 0.044715f*x3)));
}

// ---------------------------------------------------------------------------
// Init
// ---------------------------------------------------------------------------
__device__ __forceinline__ float mv0_val(int a, float x, float y, float z) {
    if (a == 14) return 1.f;
    if (a == 13) return -x;
    if (a == 12) return y;
    if (a == 11) return -z;
    return 0.f;
}

__global__ void k_init(const float* __restrict__ inputs,
                       const float* __restrict__ win_mv,  // (16,1,9)
                       const float* __restrict__ win_bs,  // (32,)
                       float* __restrict__ Smv, float* __restrict__ Ss) {
    int wid = threadIdx.x >> 5, lane = threadIdx.x & 31;
    int tok = blockIdx.x*8 + wid;
    if (tok >= NTOK) return;
    float x = inputs[tok*3+0], y = inputs[tok*3+1], z = inputs[tok*3+2];
    int a = lane & 15;
    int g = (int)((GRADE_P >> (4*a)) & 15);
    int p = (int)((PART_P  >> (4*a)) & 15);
    int h0 = (HAS0_M >> a) & 1;
    float va = mv0_val(a,x,y,z), vp = mv0_val(p,x,y,z);
    for (int oi = lane; oi < 256; oi += 32) {
        int o = oi >> 4;
        float v = __ldg(&win_mv[o*9+g]) * va;
        if (h0) v += __ldg(&win_mv[o*9+4+g]) * vp;
        Smv[(size_t)tok*256 + oi] = v;
    }
    Ss[(size_t)tok*32 + lane] = __ldg(&win_bs[lane]);
}

// ---------------------------------------------------------------------------
// Equi-linear with fused optional LayerNorm, BASIS sparsity, x in registers.
// One warp = one token, 8 warps / 256 threads per block (4 blocks/SM resident).
// ---------------------------------------------------------------------------
template<int I, int O, int SI, int SO, bool RES, bool LN>
__global__ __launch_bounds__(256) void k_equi(
        const float* __restrict__ xmv, const float* __restrict__ xs,
        const float* __restrict__ wmv, const float* __restrict__ wsm,
        const float* __restrict__ wms, const float* __restrict__ wss,
        const float* __restrict__ rmv, const float* __restrict__ rs,
        float* __restrict__ ymv, float* __restrict__ ys) {
    constexpr int WF = O*I*9;
    __shared__ float s_wk[WF];          // relaid out: [k][o][i]
    __shared__ float s_ts[8][SI + I];   // raw s (SI) then x[:,0] (I)
    __shared__ float s_ex[8][O];        // blade-0 scalar->mv contributions
    int tid = threadIdx.x;
    for (int idx = tid; idx < WF; idx += 256) {
        int o = idx / (I*9); int r = idx - o*(I*9); int i = r / 9; int k = r - i*9;
        s_wk[(k*O + o)*I + i] = wmv[idx];
    }
    int wid = tid >> 5, lane = tid & 31;
    int tok = blockIdx.x*8 + wid;
    int a = lane & 15;
    int g  = (int)((GRADE_P >> (4*a)) & 15);
    int pp = (int)((PART_P  >> (4*a)) & 15);
    int h0 = (HAS0_M >> a) & 1;
    const float* xm = xmv + (size_t)tok*(I*16);
    float xa[I], xp[I];
    #pragma unroll
    for (int i = 0; i < I; i++) { xa[i] = xm[i*16 + a]; xp[i] = xm[i*16 + pp]; }
    float sv = xs[(size_t)tok*SI + lane];
    s_ts[wid][lane] = sv;
    if (lane < I) s_ts[wid][SI + lane] = xm[lane*16];
    float r1 = 1.f, r2 = 1.f;
    if (LN) {
        float innf = ((INNER_M >> a) & 1) ? 1.f : 0.f;
        float acc = 0.f;
        #pragma unroll
        for (int i = 0; i < I; i++) acc += xa[i]*xa[i];
        acc *= innf;
        #pragma unroll
        for (int ofs = 1; ofs < 16; ofs <<= 1) acc += __shfl_xor_sync(0xffffffffu, acc, ofs);
        r1 = rsqrtf(acc*(1.f/(float)I) + 1e-6f);
        float a2 = sv*sv;
        #pragma unroll
        for (int ofs = 1; ofs < 32; ofs <<= 1) a2 += __shfl_xor_sync(0xffffffffu, a2, ofs);
        r2 = rsqrtf(a2*(1.f/(float)SI) + 1e-6f);
        #pragma unroll
        for (int i = 0; i < I; i++) { xa[i] *= r1; xp[i] *= r1; }
    }
    __syncthreads();
    // blade-0 scalar->mv contributions (wsm @ s), distributed over lanes
    for (int o = lane; o < O; o += 32) {
        const float4* w4 = reinterpret_cast<const float4*>(wsm + o*SI);
        float acc = 0.f;
        #pragma unroll
        for (int j4 = 0; j4 < SI/4; j4++) {
            float4 w = __ldg(&w4[j4]);
            acc = fmaf(w.x, s_ts[wid][j4*4+0], acc);
            acc = fmaf(w.y, s_ts[wid][j4*4+1], acc);
            acc = fmaf(w.z, s_ts[wid][j4*4+2], acc);
            acc = fmaf(w.w, s_ts[wid][j4*4+3], acc);
        }
        s_ex[wid][o] = acc * r2;
    }
    __syncwarp();
    // main mv outputs
    for (int oi = lane; oi < O*16; oi += 32) {
        int o = oi >> 4;
        const float4* w1 = reinterpret_cast<const float4*>(&s_wk[(g*O + o)*I]);
        float acc = 0.f;
        #pragma unroll
        for (int i4 = 0; i4 < I/4; i4++) {
            float4 w = w1[i4];
            acc = fmaf(w.x, xa[i4*4+0], acc);
            acc = fmaf(w.y, xa[i4*4+1], acc);
            acc = fmaf(w.z, xa[i4*4+2], acc);
            acc = fmaf(w.w, xa[i4*4+3], acc);
        }
        if (h0) {
            const float4* w2 = reinterpret_cast<const float4*>(&s_wk[((4+g)*O + o)*I]);
            #pragma unroll
            for (int i4 = 0; i4 < I/4; i4++) {
                float4 w = w2[i4];
                acc = fmaf(w.x, xp[i4*4+0], acc);
                acc = fmaf(w.y, xp[i4*4+1], acc);
                acc = fmaf(w.z, xp[i4*4+2], acc);
                acc = fmaf(w.w, xp[i4*4+3], acc);
            }
        }
        if (a == 0) acc += s_ex[wid][o];
        if (RES) acc += rmv[(size_t)tok*O*16 + oi];
        ymv[(size_t)tok*O*16 + oi] = acc;
    }
    // scalar outputs
    for (int so = lane; so < SO; so += 32) {
        const float4* ws4 = reinterpret_cast<const float4*>(wss + so*SI);
        float accs = 0.f;
        #pragma unroll
        for (int j4 = 0; j4 < SI/4; j4++) {
            float4 w = __ldg(&ws4[j4]);
            accs = fmaf(w.x, s_ts[wid][j4*4+0], accs);
            accs = fmaf(w.y, s_ts[wid][j4*4+1], accs);
            accs = fmaf(w.z, s_ts[wid][j4*4+2], accs);
            accs = fmaf(w.w, s_ts[wid][j4*4+3], accs);
        }
        const float4* wm4 = reinterpret_cast<const float4*>(wms + so*I);
        float accm = 0.f;
        #pragma unroll
        for (int i4 = 0; i4 < I/4; i4++) {
            float4 w = __ldg(&wm4[i4]);
            accm = fmaf(w.x, s_ts[wid][SI + i4*4+0], accm);
            accm = fmaf(w.y, s_ts[wid][SI + i4*4+1], accm);
            accm = fmaf(w.z, s_ts[wid][SI + i4*4+2], accm);
            accm = fmaf(w.w, s_ts[wid][SI + i4*4+3], accm);
        }
        float acc = accs*r2 + accm*r1;
        if (RES) acc += rs[(size_t)tok*SO + so];
        ys[(size_t)tok*SO + so] = acc;
    }
}

// ---------------------------------------------------------------------------
// Flash attention (fp32). Q/K compacted to the 20 effective score dims
// (8 inner blades x 2 mv channels + 4 scalars); V keeps all 36 dims.
// Score phase: 4x4 register tiles.  O-phase: 4 rows x 9 dims x 4-way key split.
// ---------------------------------------------------------------------------
#define KQ 20
#define KQP 21
#define KD 36
#define KDP 37
#define PSP 65
__global__ __launch_bounds__(256) void k_attn(
        const float* __restrict__ qkv_mv, const float* __restrict__ qkv_s,
        float* __restrict__ omv, float* __restrict__ os) {
    __shared__ float qs[64*KQP], ks[64*KQP], vs[64*KDP];
    __shared__ float ps[64*PSP];
    __shared__ float m_s[64], l_s[64], corr_s[64];
    int tid = threadIdx.x;
    int bh = blockIdx.y, b = bh >> 3, h = bh & 7;
    int qtok0 = b*NN + blockIdx.x*64;
    // load compact q
    for (int idx = tid; idx < 64*KQ; idx += 256) {
        int r = idx / KQ, d = idx - r*KQ;
        int t = qtok0 + r;
        float v;
        if (d < 16) {
            int c = d >> 3, ib = (int)((IB_P >> (4*(d & 7))) & 15);
            v = qkv_mv[(size_t)t*768 + (h*2+c)*16 + ib];
        } else v = qkv_s[(size_t)t*96 + h*4 + (d-16)];
        qs[r*KQP + d] = v;
    }
    if (tid < 64) { m_s[tid] = -1e30f; l_s[tid] = 0.f; }
    // o-phase mapping
    int rq  = tid >> 4;
    int ogl = (tid >> 2) & 3;
    int kspl= tid & 3;
    float o4[4][9];
    #pragma unroll
    for (int r = 0; r < 4; r++)
        #pragma unroll
        for (int d = 0; d < 9; d++) o4[r][d] = 0.f;
    int kl = tid & 15;   // score phase: rq rows x kl key-quads
    int ktok0 = b*NN;
    for (int kt = 0; kt < NN/64; kt++) {
        __syncthreads();
        // load compact k
        for (int idx = tid; idx < 64*KQ; idx += 256) {
            int r = idx / KQ, d = idx - r*KQ;
            int t = ktok0 + kt*64 + r;
            float v;
            if (d < 16) {
                int c = d >> 3, ib = (int)((IB_P >> (4*(d & 7))) & 15);
                v = qkv_mv[(size_t)t*768 + 256 + (h*2+c)*16 + ib];
            } else v = qkv_s[(size_t)t*96 + 32 + h*4 + (d-16)];
            ks[r*KQP + d] = v;
        }
        // load full v
        for (int idx = tid; idx < 64*KD; idx += 256) {
            int r = idx / KD, d = idx - r*KD;
            int t = ktok0 + kt*64 + r;
            float v;
            if (d < 32) { int c = d >> 4, i = d & 15;
                v = qkv_mv[(size_t)t*768 + 512 + (h*2+c)*16 + i]; }
            else v = qkv_s[(size_t)t*96 + 64 + h*4 + (d-32)];
            vs[r*KDP + d] = v;
        }
        __syncthreads();
        // ---- score phase (20 dims) ----
        float sc[4][4];
        #pragma unroll
        for (int i = 0; i < 4; i++)
            #pragma unroll
            for (int j = 0; j < 4; j++) sc[i][j] = 0.f;
        #pragma unroll 4
        for (int d = 0; d < KQ; d++) {
            float q4[4], k4[4];
            #pragma unroll
            for (int i = 0; i < 4; i++) q4[i] = qs[(rq*4+i)*KQP + d];
            #pragma unroll
            for (int j = 0; j < 4; j++) k4[j] = ks[(kl*4+j)*KQP + d];
            #pragma unroll
            for (int i = 0; i < 4; i++)
                #pragma unroll
                for (int j = 0; j < 4; j++) sc[i][j] = fmaf(q4[i], k4[j], sc[i][j]);
        }
        #pragma unroll
        for (int i = 0; i < 4; i++) {
            float tm = -1e30f;
            #pragma unroll
            for (int j = 0; j < 4; j++) { sc[i][j] *= SCALE; tm = fmaxf(tm, sc[i][j]); }
            #pragma unroll
            for (int ofs = 1; ofs < 16; ofs <<= 1)
                tm = fmaxf(tm, __shfl_xor_sync(0xffffffffu, tm, ofs));
            int row = rq*4 + i;
            float mo = m_s[row];
            float nm = fmaxf(mo, tm);
            float sum = 0.f;
            #pragma unroll
            for (int j = 0; j < 4; j++) {
                float pv = __expf(sc[i][j] - nm);
                sum += pv;
                ps[row*PSP + kl*4 + j] = pv;
            }
            #pragma unroll
            for (int ofs = 1; ofs < 16; ofs <<= 1)
                sum += __shfl_xor_sync(0xffffffffu, sum, ofs);
            if (kl == 0) {
                float corr = __expf(mo - nm);
                corr_s[row] = corr;
                m_s[row] = nm;
                l_s[row] = l_s[row]*corr + sum;
            }
        }
        __syncthreads();
        // ---- o accumulation phase ----
        float c4[4];
        #pragma unroll
        for (int r = 0; r < 4; r++) c4[r] = corr_s[rq*4 + r];
        #pragma unroll
        for (int r = 0; r < 4; r++)
            #pragma unroll
            for (int d = 0; d < 9; d++) o4[r][d] *= c4[r];
        int key0 = kspl*16;
        for (int kk = 0; kk < 16; kk++) {
            int key = key0 + kk;
            float p0 = ps[(rq*4+0)*PSP + key];
            float p1 = ps[(rq*4+1)*PSP + key];
            float p2 = ps[(rq*4+2)*PSP + key];
            float p3 = ps[(rq*4+3)*PSP + key];
            const float* vrow = &vs[key*KDP + ogl*9];
            #pragma unroll
            for (int d = 0; d < 9; d++) {
                float v = vrow[d];
                o4[0][d] = fmaf(p0, v, o4[0][d]);
                o4[1][d] = fmaf(p1, v, o4[1][d]);
                o4[2][d] = fmaf(p2, v, o4[2][d]);
                o4[3][d] = fmaf(p3, v, o4[3][d]);
            }
        }
    }
    // reduce key splits
    #pragma unroll
    for (int r = 0; r < 4; r++)
        #pragma unroll
        for (int d = 0; d < 9; d++) {
            float v = o4[r][d];
            v += __shfl_xor_sync(0xffffffffu, v, 1);
            v += __shfl_xor_sync(0xffffffffu, v, 2);
            o4[r][d] = v;
        }
    if (kspl == 0) {
        #pragma unroll
        for (int r = 0; r < 4; r++) {
            int row = rq*4 + r;
            float inv = 1.f / l_s[row];
            int t = qtok0 + row;
            #pragma unroll
            for (int dd = 0; dd < 9; dd++) {
                int d = ogl*9 + dd;
                float val = o4[r][dd]*inv;
                if (d < 32) omv[(size_t)t*256 + (h*2 + (d>>4))*16 + (d&15)] = val;
                else        os[(size_t)t*32 + h*4 + (d-32)] = val;
            }
        }
    }
}

// ---------------------------------------------------------------------------
// Geometric product + gelu gates. Fully unrolled compile-time product table.
// One thread per (token, channel); no shared memory.
// ---------------------------------------------------------------------------
__global__ __launch_bounds__(256) void k_geo(
        const float* __restrict__ hmv, const float* __restrict__ hs,
        float* __restrict__ gp_mv, float* __restrict__ sh) {
    int gid = blockIdx.x*256 + threadIdx.x;
    int tok = gid >> 4, ch = gid & 15;
    const float4* ap = reinterpret_cast<const float4*>(hmv + (size_t)tok*512 + ch*16);
    const float4* bp = reinterpret_cast<const float4*>(hmv + (size_t)tok*512 + 256 + ch*16);
    float av[16], bv[16];
    #pragma unroll
    for (int q = 0; q < 4; q++) {
        float4 va = ap[q], vb = bp[q];
        av[4*q+0]=va.x; av[4*q+1]=va.y; av[4*q+2]=va.z; av[4*q+3]=va.w;
        bv[4*q+0]=vb.x; bv[4*q+1]=vb.y; bv[4*q+2]=vb.z; bv[4*q+3]=vb.w;
    }
    float g[16];
    #pragma unroll
    for (int k = 0; k < 16; k++) g[k] = 0.f;
    #pragma unroll
    for (int i = 0; i < 16; i++) {
        #pragma unroll
        for (int j = 0; j < 16; j++) {
            const int sg = gp_sign(i, j);
            if (sg != 0) {
                const int k = gp_out(i, j);
                g[k] = fmaf((sg > 0 ? av[i] : -av[i]), bv[j], g[k]);
            }
        }
    }
    float gate = gelu_tanh(g[0]);
    float4* op = reinterpret_cast<float4*>(gp_mv + (size_t)tok*256 + ch*16);
    #pragma unroll
    for (int q = 0; q < 4; q++) {
        float4 v;
        v.x = g[4*q+0]*gate; v.y = g[4*q+1]*gate;
        v.z = g[4*q+2]*gate; v.w = g[4*q+3]*gate;
        op[q] = v;
    }
    // scalar gates: 32 outs per token, 16 threads -> 2 each
    #pragma unroll
    for (int r = 0; r < 2; r++) {
        int j = ch + r*16;
        float x1 = hs[(size_t)tok*64 + j];
        float x2 = hs[(size_t)tok*64 + 32 + j];
        sh[(size_t)tok*32 + j] = x1 * gelu_tanh(x2);
    }
}

// ---------------------------------------------------------------------------
// Final readout
// ---------------------------------------------------------------------------
__global__ void k_final(const float* __restrict__ Smv, const float* __restrict__ Ss,
                        const float* __restrict__ wout_mv, const float* __restrict__ wout_sm,
                        float* __restrict__ out) {
    __shared__ float red[256];
    int b = blockIdx.x;
    float acc = 0.f;
    for (int n = threadIdx.x; n < NN; n += 256) {
        size_t t = (size_t)b*NN + n;
        float v = 0.f;
        #pragma unroll
        for (int i = 0; i < 16; i++) v = fmaf(__ldg(&wout_mv[i*9]), Smv[t*256 + i*16], v);
        #pragma unroll
        for (int j = 0; j < 32; j++) v = fmaf(__ldg(&wout_sm[j]), Ss[t*32 + j], v);
        acc += v;
    }
    red[threadIdx.x] = acc;
    __syncthreads();
    for (int s = 128; s; s >>= 1) {
        if (threadIdx.x < s) red[threadIdx.x] += red[threadIdx.x + s];
        __syncthreads();
    }
    if (threadIdx.x == 0) out[b] = red[0] * (1.f/NN);
}

// ---------------------------------------------------------------------------
// Host
// ---------------------------------------------------------------------------
template<int I, int O, int SI, int SO, bool RES, bool LN>
static void launch_equi(const float* xmv, const float* xs,
                        const float* wmv, const float* wsm,
                        const float* wms, const float* wss,
                        const float* rmv, const float* rs,
                        float* ymv, float* ys) {
    k_equi<I,O,SI,SO,RES,LN><<<NTOK/8, 256>>>(xmv, xs, wmv, wsm, wms, wss,
                                              rmv, rs, ymv, ys);
}

extern "C" void kernel_launch(void* const* d_in, const int* in_sizes, int n_in,
                              void* d_out, int out_size) {
    const float* inputs    = (const float*)d_in[0];
    const float* win_mv    = (const float*)d_in[1];
    const float* win_bs    = (const float*)d_in[3];
    const float* qkv_wmv   = (const float*)d_in[4];
    const float* qkv_wsm   = (const float*)d_in[5];
    const float* qkv_wms   = (const float*)d_in[6];
    const float* qkv_wss   = (const float*)d_in[7];
    const float* out_wmv   = (const float*)d_in[8];
    const float* out_wsm   = (const float*)d_in[9];
    const float* out_wms   = (const float*)d_in[10];
    const float* out_wss   = (const float*)d_in[11];
    const float* m1_wmv    = (const float*)d_in[12];
    const float* m1_wsm    = (const float*)d_in[13];
    const float* m1_wms    = (const float*)d_in[14];
    const float* m1_wss    = (const float*)d_in[15];
    const float* m2_wmv    = (const float*)d_in[16];
    const float* m2_wsm    = (const float*)d_in[17];
    const float* m2_wms    = (const float*)d_in[18];
    const float* m2_wss    = (const float*)d_in[19];
    const float* wout_mv   = (const float*)d_in[20];
    const float* wout_sm   = (const float*)d_in[21];
    float* out = (float*)d_out;

    int L = in_sizes[4] / (48*16*9);

    float *Smv, *Ss, *Qmv, *Qs, *Amv, *As;
    cudaGetSymbolAddress((void**)&Smv, g_S_mv);
    cudaGetSymbolAddress((void**)&Ss,  g_S_s);
    cudaGetSymbolAddress((void**)&Qmv, g_Q_mv);
    cudaGetSymbolAddress((void**)&Qs,  g_Q_s);
    cudaGetSymbolAddress((void**)&Amv, g_A_mv);
    cudaGetSymbolAddress((void**)&As,  g_A_s);

    k_init<<<NTOK/8, 256>>>(inputs, win_mv, win_bs, Smv, Ss);

    for (int l = 0; l < L; l++) {
        // --- attention block (LN fused into qkv equi) ---
        launch_equi<16,48,32,96,false,true>(Smv, Ss,
            qkv_wmv + (size_t)l*48*16*9, qkv_wsm + (size_t)l*48*32,
            qkv_wms + (size_t)l*96*16,   qkv_wss + (size_t)l*96*32,
            nullptr, nullptr, Qmv, Qs);
        k_attn<<<dim3(NN/64, BB*HH), 256>>>(Qmv, Qs, Amv, As);
        launch_equi<16,16,32,32,true,false>(Amv, As,
            out_wmv + (size_t)l*16*16*9, out_wsm + (size_t)l*16*32,
            out_wms + (size_t)l*32*16,   out_wss + (size_t)l*32*32,
            Smv, Ss, Smv, Ss);
        // --- mlp block (LN fused into mlp1 equi) ---
        launch_equi<16,32,32,64,false,true>(Smv, Ss,
            m1_wmv + (size_t)l*32*16*9, m1_wsm + (size_t)l*32*32,
            m1_wms + (size_t)l*64*16,   m1_wss + (size_t)l*64*32,
            nullptr, nullptr, Qmv, Qs);
        k_geo<<<NTOK*16/256, 256>>>(Qmv, Qs, Amv, As);
        launch_equi<16,16,32,32,true,false>(Amv, As,
            m2_wmv + (size_t)l*16*16*9, m2_wsm + (size_t)l*16*32,
            m2_wms + (size_t)l*32*16,   m2_wss + (size_t)l*32*32,
            Smv, Ss, Smv, Ss);
    }

    k_final<<<BB, 256>>>(Smv, Ss, wout_mv, wout_sm, out);
}

// round 17
// speedup vs baseline: 1.8427x; 1.1201x over previous
#include <cuda_runtime.h>
#include <math.h>

// Problem constants (fixed by setup_inputs)
#define BB 8
#define NN 1024
#define NTOK (BB*NN)   // 8192
#define HH 8
#define SCALE 0.2236067977499790f  // 1/sqrt(20)

// ---------------------------------------------------------------------------
// Compile-time blade tables.
// idx: 0:(),1:(0),2:(1),3:(2),4:(3),5:(01),6:(02),7:(03),8:(12),9:(13),10:(23),
//      11:(012),12:(013),13:(023),14:(123),15:(0123)
// ---------------------------------------------------------------------------
constexpr int BL_GRADE[16]= {0,1,1,1,1,2,2,2,2,2,2,3,3,3,3,4};
constexpr int BL_PART[16] = {1,0,5,6,7,2,3,4,11,12,13,8,9,10,15,14}; // blade^e0
constexpr unsigned INNER_M = 0x471Du;   // 1 if e0 not in blade
constexpr unsigned HAS0_M  = 0xB8E2u;   // 1 if e0 in blade
// Inner blades (INNER=1), ascending: {0,2,3,4,8,9,10,14};
// IBS_P nibble[a] = compact slot of blade a (valid only when INNER_M bit set)
constexpr unsigned long long IBS_P = 0x0700065400032100ULL;

constexpr unsigned long long pack4(const int (&t)[16]) {
    unsigned long long v = 0;
    for (int i = 0; i < 16; i++) v |= (unsigned long long)t[i] << (4*i);
    return v;
}
constexpr unsigned long long GRADE_P = pack4(BL_GRADE);
constexpr unsigned long long PART_P  = pack4(BL_PART);

__host__ __device__ constexpr int gp_sign(int i, int j) {  // sign of blade_i*blade_j, 0 if e0*e0
    const int M[16] = {0,1,2,4,8,3,5,9,6,10,12,7,11,13,14,15};
    int mi = M[i], mj = M[j];
    if (mi & mj & 1) return 0;
    int inv = 0;
    for (int y = 0; y < 4; y++)
        if ((mj >> y) & 1)
            for (int z = y+1; z < 4; z++) inv += (mi >> z) & 1;
    return (inv & 1) ? -1 : 1;
}
__host__ __device__ constexpr int gp_out(int i, int j) {
    const int M[16]   = {0,1,2,4,8,3,5,9,6,10,12,7,11,13,14,15};
    const int M2I[16] = {0,1,2,5,3,6,8,11,4,7,9,12,10,13,14,15};
    return M2I[M[i] ^ M[j]];
}

// Scratch (device globals; no allocation allowed). 16B-aligned: several of
// these are accessed through float4* casts.
__device__ __align__(16) float g_S_mv[NTOK*256];
__device__ __align__(16) float g_S_s [NTOK*32];
__device__ __align__(16) float g_Q_mv[NTOK*768];   // mlp hidden mv (32 ch)
__device__ __align__(16) float g_Q_s [NTOK*96];    // mlp hidden s (64)
__device__ __align__(16) float g_A_mv[NTOK*256];   // attn out mv / geo product
__device__ __align__(16) float g_A_s [NTOK*32];    // attn out s / gated scalars
// Attention-friendly qkv layouts
__device__ __align__(16) float g_qc[(size_t)BB*HH*NN*20];
__device__ __align__(16) float g_kc[(size_t)BB*HH*NN*20];
__device__ __align__(16) float g_vc[(size_t)BB*HH*NN*48];

__device__ __forceinline__ float gelu_tanh(float x) {
    float x3 = x*x*x;
    return 0.5f*x*(1.f + tanhf(0.7978845608028654f*(x + 0.044715f*x3)));
}

// ---------------------------------------------------------------------------
// Init
// ---------------------------------------------------------------------------
__device__ __forceinline__ float mv0_val(int a, float x, float y, float z) {
    if (a == 14) return 1.f;
    if (a == 13) return -x;
    if (a == 12) return y;
    if (a == 11) return -z;
    return 0.f;
}

__global__ void k_init(const float* __restrict__ inputs,
                       const float* __restrict__ win_mv,  // (16,1,9)
                       const float* __restrict__ win_bs,  // (32,)
                       float* __restrict__ Smv, float* __restrict__ Ss) {
    int wid = threadIdx.x >> 5, lane = threadIdx.x & 31;
    int tok = blockIdx.x*8 + wid;
    if (tok >= NTOK) return;
    float x = inputs[tok*3+0], y = inputs[tok*3+1], z = inputs[tok*3+2];
    int a = lane & 15;
    int g = (int)((GRADE_P >> (4*a)) & 15);
    int p = (int)((PART_P  >> (4*a)) & 15);
    int h0 = (HAS0_M >> a) & 1;
    float va = mv0_val(a,x,y,z), vp = mv0_val(p,x,y,z);
    for (int oi = lane; oi < 256; oi += 32) {
        int o = oi >> 4;
        float v = __ldg(&win_mv[o*9+g]) * va;
        if (h0) v += __ldg(&win_mv[o*9+4+g]) * vp;
        Smv[(size_t)tok*256 + oi] = v;
    }
    Ss[(size_t)tok*32 + lane] = __ldg(&win_bs[lane]);
}

// ---------------------------------------------------------------------------
// Equi-linear with fused optional LayerNorm, BASIS sparsity, x in registers.
// One warp = one token, 8 warps / 256 threads per block.
// If QKV: redirect outputs to attention-friendly compact buffers qc/kc/vc.
// ---------------------------------------------------------------------------
template<int I, int O, int SI, int SO, bool RES, bool LN, bool QKV>
__global__ __launch_bounds__(256) void k_equi(
        const float* __restrict__ xmv, const float* __restrict__ xs,
        const float* __restrict__ wmv, const float* __restrict__ wsm,
        const float* __restrict__ wms, const float* __restrict__ wss,
        const float* __restrict__ rmv, const float* __restrict__ rs,
        float* __restrict__ ymv, float* __restrict__ ys,
        float* __restrict__ qc, float* __restrict__ kc, float* __restrict__ vc) {
    constexpr int WF = O*I*9;
    __shared__ float s_wk[WF];          // relaid out: [k][o][i]
    __shared__ float s_ts[8][SI + I];   // raw s (SI) then x[:,0] (I)
    __shared__ float s_ex[8][O];        // blade-0 scalar->mv contributions
    int tid = threadIdx.x;
    for (int idx = tid; idx < WF; idx += 256) {
        int o = idx / (I*9); int r = idx - o*(I*9); int i = r / 9; int k = r - i*9;
        s_wk[(k*O + o)*I + i] = wmv[idx];
    }
    int wid = tid >> 5, lane = tid & 31;
    int tok = blockIdx.x*8 + wid;
    int a = lane & 15;
    int g  = (int)((GRADE_P >> (4*a)) & 15);
    int pp = (int)((PART_P  >> (4*a)) & 15);
    int h0 = (HAS0_M >> a) & 1;
    int inner = (INNER_M >> a) & 1;
    int slot = (int)((IBS_P >> (4*a)) & 15);
    int bb = tok >> 10, nn2 = tok & 1023;
    const float* xm = xmv + (size_t)tok*(I*16);
    float xa[I], xp[I];
    #pragma unroll
    for (int i = 0; i < I; i++) { xa[i] = xm[i*16 + a]; xp[i] = xm[i*16 + pp]; }
    float sv = xs[(size_t)tok*SI + lane];
    s_ts[wid][lane] = sv;
    if (lane < I) s_ts[wid][SI + lane] = xm[lane*16];
    float r1 = 1.f, r2 = 1.f;
    if (LN) {
        float innf = inner ? 1.f : 0.f;
        float acc = 0.f;
        #pragma unroll
        for (int i = 0; i < I; i++) acc += xa[i]*xa[i];
        acc *= innf;
        #pragma unroll
        for (int ofs = 1; ofs < 16; ofs <<= 1) acc += __shfl_xor_sync(0xffffffffu, acc, ofs);
        r1 = rsqrtf(acc*(1.f/(float)I) + 1e-6f);
        float a2 = sv*sv;
        #pragma unroll
        for (int ofs = 1; ofs < 32; ofs <<= 1) a2 += __shfl_xor_sync(0xffffffffu, a2, ofs);
        r2 = rsqrtf(a2*(1.f/(float)SI) + 1e-6f);
        #pragma unroll
        for (int i = 0; i < I; i++) { xa[i] *= r1; xp[i] *= r1; }
    }
    __syncthreads();
    // blade-0 scalar->mv contributions (wsm @ s), distributed over lanes
    for (int o = lane; o < O; o += 32) {
        const float4* w4 = reinterpret_cast<const float4*>(wsm + o*SI);
        float acc = 0.f;
        #pragma unroll
        for (int j4 = 0; j4 < SI/4; j4++) {
            float4 w = __ldg(&w4[j4]);
            acc = fmaf(w.x, s_ts[wid][j4*4+0], acc);
            acc = fmaf(w.y, s_ts[wid][j4*4+1], acc);
            acc = fmaf(w.z, s_ts[wid][j4*4+2], acc);
            acc = fmaf(w.w, s_ts[wid][j4*4+3], acc);
        }
        s_ex[wid][o] = acc * r2;
    }
    __syncwarp();
    // main mv outputs
    for (int oi = lane; oi < O*16; oi += 32) {
        int o = oi >> 4;
        const float4* w1 = reinterpret_cast<const float4*>(&s_wk[(g*O + o)*I]);
        float acc = 0.f;
        #pragma unroll
        for (int i4 = 0; i4 < I/4; i4++) {
            float4 w = w1[i4];
            acc = fmaf(w.x, xa[i4*4+0], acc);
            acc = fmaf(w.y, xa[i4*4+1], acc);
            acc = fmaf(w.z, xa[i4*4+2], acc);
            acc = fmaf(w.w, xa[i4*4+3], acc);
        }
        if (h0) {
            const float4* w2 = reinterpret_cast<const float4*>(&s_wk[((4+g)*O + o)*I]);
            #pragma unroll
            for (int i4 = 0; i4 < I/4; i4++) {
                float4 w = w2[i4];
                acc = fmaf(w.x, xp[i4*4+0], acc);
                acc = fmaf(w.y, xp[i4*4+1], acc);
                acc = fmaf(w.z, xp[i4*4+2], acc);
                acc = fmaf(w.w, xp[i4*4+3], acc);
            }
        }
        if (a == 0) acc += s_ex[wid][o];
        if (QKV) {
            if (o < 32) {
                if (inner) {
                    int hh = (o & 15) >> 1, c = o & 1;
                    float* dst = (o < 16) ? qc : kc;
                    dst[(((size_t)bb*HH + hh)*NN + nn2)*20 + c*8 + slot] = acc;
                }
            } else {
                int hh = (o - 32) >> 1, c = (o - 32) & 1;
                int d = c*16 + a;
                vc[(((size_t)bb*HH + hh)*NN + nn2)*48 + (d/9)*12 + (d%9)] = acc;
            }
        } else {
            if (RES) acc += rmv[(size_t)tok*O*16 + oi];
            ymv[(size_t)tok*O*16 + oi] = acc;
        }
    }
    // scalar outputs
    for (int so = lane; so < SO; so += 32) {
        const float4* ws4 = reinterpret_cast<const float4*>(wss + so*SI);
        float accs = 0.f;
        #pragma unroll
        for (int j4 = 0; j4 < SI/4; j4++) {
            float4 w = __ldg(&ws4[j4]);
            accs = fmaf(w.x, s_ts[wid][j4*4+0], accs);
            accs = fmaf(w.y, s_ts[wid][j4*4+1], accs);
            accs = fmaf(w.z, s_ts[wid][j4*4+2], accs);
            accs = fmaf(w.w, s_ts[wid][j4*4+3], accs);
        }
        const float4* wm4 = reinterpret_cast<const float4*>(wms + so*I);
        float accm = 0.f;
        #pragma unroll
        for (int i4 = 0; i4 < I/4; i4++) {
            float4 w = __ldg(&wm4[i4]);
            accm = fmaf(w.x, s_ts[wid][SI + i4*4+0], accm);
            accm = fmaf(w.y, s_ts[wid][SI + i4*4+1], accm);
            accm = fmaf(w.z, s_ts[wid][SI + i4*4+2], accm);
            accm = fmaf(w.w, s_ts[wid][SI + i4*4+3], accm);
        }
        float acc = accs*r2 + accm*r1;
        if (QKV) {
            if (so < 64) {
                int s2 = so & 31;
                int hh = s2 >> 2;
                float* dst = (so < 32) ? qc : kc;
                dst[(((size_t)bb*HH + hh)*NN + nn2)*20 + 16 + (s2 & 3)] = acc;
            } else {
                int s2 = so - 64, hh = s2 >> 2;
                int d = 32 + (s2 & 3);   // dims 32..35 -> group 3, off d-27
                vc[(((size_t)bb*HH + hh)*NN + nn2)*48 + 36 + (d - 27)] = acc;
            }
        } else {
            if (RES) acc += rs[(size_t)tok*SO + so];
            ys[(size_t)tok*SO + so] = acc;
        }
    }
}

// ---------------------------------------------------------------------------
// Flash attention (fp32) on precompacted head-major q/k (20 dims) and v (48-
// padded 36 dims). Coalesced float4 tile loads. Score: 4x4 register tiles.
// O-phase: 4 rows x 9 dims x 4-way key split, vectorized ps/v reads.
// ---------------------------------------------------------------------------
#define KQ 20
#define KQP 21
#define VROW 48
#define PSR 68
__global__ __launch_bounds__(256, 3) void k_attn(
        const float* __restrict__ qc, const float* __restrict__ kc,
        const float* __restrict__ vc,
        float* __restrict__ omv, float* __restrict__ os) {
    __shared__ float qs[64*KQP], ks[64*KQP], vs[64*VROW];
    __shared__ float ps[64*PSR];           // transposed: [key][row]
    __shared__ float m_s[64], l_s[64], corr_s[64];
    int tid = threadIdx.x;
    int bh = blockIdx.y, b = bh >> 3, h = bh & 7;
    int q0 = blockIdx.x*64;
    // load compact q (64x20 floats = 320 float4)
    {
        const float4* src = reinterpret_cast<const float4*>(
            qc + ((size_t)bh*NN + q0)*20);
        for (int idx = tid; idx < 320; idx += 256) {
            float4 v = src[idx];
            int r = idx/5, p = idx - r*5;
            float* dq = &qs[r*KQP + p*4];
            dq[0]=v.x; dq[1]=v.y; dq[2]=v.z; dq[3]=v.w;
        }
    }
    if (tid < 64) { m_s[tid] = -1e30f; l_s[tid] = 0.f; }
    int rq  = tid >> 4;          // 0..15: 4-row group
    int ogl = (tid >> 2) & 3;    // 0..3: 9-dim group
    int kspl= tid & 3;           // 0..3: key split
    int kl  = tid & 15;          // score phase: key quad
    float o4[4][9];
    #pragma unroll
    for (int r = 0; r < 4; r++)
        #pragma unroll
        for (int d = 0; d < 9; d++) o4[r][d] = 0.f;
    for (int kt = 0; kt < NN/64; kt++) {
        __syncthreads();
        {
            const float4* ksrc = reinterpret_cast<const float4*>(
                kc + ((size_t)bh*NN + kt*64)*20);
            for (int idx = tid; idx < 320; idx += 256) {
                float4 v = ksrc[idx];
                int r = idx/5, p = idx - r*5;
                float* dk = &ks[r*KQP + p*4];
                dk[0]=v.x; dk[1]=v.y; dk[2]=v.z; dk[3]=v.w;
            }
            const float4* vsrc = reinterpret_cast<const float4*>(
                vc + ((size_t)bh*NN + kt*64)*48);
            float4* vdst = reinterpret_cast<float4*>(vs);
            for (int idx = tid; idx < 768; idx += 256) vdst[idx] = vsrc[idx];
        }
        __syncthreads();
        // ---- score phase (20 dims) ----
        float sc[4][4];
        #pragma unroll
        for (int i = 0; i < 4; i++)
            #pragma unroll
            for (int j = 0; j < 4; j++) sc[i][j] = 0.f;
        #pragma unroll 4
        for (int d = 0; d < KQ; d++) {
            float q4[4], k4[4];
            #pragma unroll
            for (int i = 0; i < 4; i++) q4[i] = qs[(rq*4+i)*KQP + d];
            #pragma unroll
            for (int j = 0; j < 4; j++) k4[j] = ks[(kl*4+j)*KQP + d];
            #pragma unroll
            for (int i = 0; i < 4; i++)
                #pragma unroll
                for (int j = 0; j < 4; j++) sc[i][j] = fmaf(q4[i], k4[j], sc[i][j]);
        }
        #pragma unroll
        for (int i = 0; i < 4; i++) {
            float tm = -1e30f;
            #pragma unroll
            for (int j = 0; j < 4; j++) { sc[i][j] *= SCALE; tm = fmaxf(tm, sc[i][j]); }
            #pragma unroll
            for (int ofs = 1; ofs < 16; ofs <<= 1)
                tm = fmaxf(tm, __shfl_xor_sync(0xffffffffu, tm, ofs));
            int row = rq*4 + i;
            float mo = m_s[row];
            float nm = fmaxf(mo, tm);
            float sum = 0.f;
            #pragma unroll
            for (int j = 0; j < 4; j++) {
                sc[i][j] = __expf(sc[i][j] - nm);   // reuse sc as p
                sum += sc[i][j];
            }
            #pragma unroll
            for (int ofs = 1; ofs < 16; ofs <<= 1)
                sum += __shfl_xor_sync(0xffffffffu, sum, ofs);
            if (kl == 0) {
                float corr = __expf(mo - nm);
                corr_s[row] = corr;
                m_s[row] = nm;
                l_s[row] = l_s[row]*corr + sum;
            }
        }
        // transposed ps writes: 4 rows contiguous -> STS.128
        #pragma unroll
        for (int j = 0; j < 4; j++) {
            float4 w = make_float4(sc[0][j], sc[1][j], sc[2][j], sc[3][j]);
            *reinterpret_cast<float4*>(&ps[(kl*4+j)*PSR + rq*4]) = w;
        }
        __syncthreads();
        // ---- o accumulation phase ----
        float c4[4];
        #pragma unroll
        for (int r = 0; r < 4; r++) c4[r] = corr_s[rq*4 + r];
        #pragma unroll
        for (int r = 0; r < 4; r++)
            #pragma unroll
            for (int d = 0; d < 9; d++) o4[r][d] *= c4[r];
        #pragma unroll 4
        for (int kk = 0; kk < 16; kk++) {
            int key = kk*4 + kspl;                  // interleaved key split
            float4 p4 = *reinterpret_cast<const float4*>(&ps[key*PSR + rq*4]);
            const float4* vr = reinterpret_cast<const float4*>(&vs[key*VROW + ogl*12]);
            float4 va = vr[0], vb = vr[1], vg = vr[2];
            float vv[9] = {va.x,va.y,va.z,va.w, vb.x,vb.y,vb.z,vb.w, vg.x};
            #pragma unroll
            for (int d = 0; d < 9; d++) {
                o4[0][d] = fmaf(p4.x, vv[d], o4[0][d]);
                o4[1][d] = fmaf(p4.y, vv[d], o4[1][d]);
                o4[2][d] = fmaf(p4.z, vv[d], o4[2][d]);
                o4[3][d] = fmaf(p4.w, vv[d], o4[3][d]);
            }
        }
    }
    // reduce key splits (lanes xor 1,2 within groups of 4)
    #pragma unroll
    for (int r = 0; r < 4; r++)
        #pragma unroll
        for (int d = 0; d < 9; d++) {
            float v = o4[r][d];
            v += __shfl_xor_sync(0xffffffffu, v, 1);
            v += __shfl_xor_sync(0xffffffffu, v, 2);
            o4[r][d] = v;
        }
    if (kspl == 0) {
        #pragma unroll
        for (int r = 0; r < 4; r++) {
            int row = rq*4 + r;
            float inv = 1.f / l_s[row];
            int t = b*NN + q0 + row;
            #pragma unroll
            for (int dd = 0; dd < 9; dd++) {
                int d = ogl*9 + dd;
                float val = o4[r][dd]*inv;
                if (d < 32) omv[(size_t)t*256 + (h*2 + (d>>4))*16 + (d&15)] = val;
                else        os[(size_t)t*32 + h*4 + (d-32)] = val;
            }
        }
    }
}

// ---------------------------------------------------------------------------
// Geometric product + gelu gates. Fully unrolled compile-time product table.
// ---------------------------------------------------------------------------
__global__ __launch_bounds__(256) void k_geo(
        const float* __restrict__ hmv, const float* __restrict__ hs,
        float* __restrict__ gp_mv, float* __restrict__ sh) {
    int gid = blockIdx.x*256 + threadIdx.x;
    int tok = gid >> 4, ch = gid & 15;
    const float4* ap = reinterpret_cast<const float4*>(hmv + (size_t)tok*512 + ch*16);
    const float4* bp = reinterpret_cast<const float4*>(hmv + (size_t)tok*512 + 256 + ch*16);
    float av[16], bv[16];
    #pragma unroll
    for (int q = 0; q < 4; q++) {
        float4 va = ap[q], vb = bp[q];
        av[4*q+0]=va.x; av[4*q+1]=va.y; av[4*q+2]=va.z; av[4*q+3]=va.w;
        bv[4*q+0]=vb.x; bv[4*q+1]=vb.y; bv[4*q+2]=vb.z; bv[4*q+3]=vb.w;
    }
    float g[16];
    #pragma unroll
    for (int k = 0; k < 16; k++) g[k] = 0.f;
    #pragma unroll
    for (int i = 0; i < 16; i++) {
        #pragma unroll
        for (int j = 0; j < 16; j++) {
            const int sg = gp_sign(i, j);
            if (sg != 0) {
                const int k = gp_out(i, j);
                g[k] = fmaf((sg > 0 ? av[i] : -av[i]), bv[j], g[k]);
            }
        }
    }
    float gate = gelu_tanh(g[0]);
    float4* op = reinterpret_cast<float4*>(gp_mv + (size_t)tok*256 + ch*16);
    #pragma unroll
    for (int q = 0; q < 4; q++) {
        float4 v;
        v.x = g[4*q+0]*gate; v.y = g[4*q+1]*gate;
        v.z = g[4*q+2]*gate; v.w = g[4*q+3]*gate;
        op[q] = v;
    }
    #pragma unroll
    for (int r = 0; r < 2; r++) {
        int j = ch + r*16;
        float x1 = hs[(size_t)tok*64 + j];
        float x2 = hs[(size_t)tok*64 + 32 + j];
        sh[(size_t)tok*32 + j] = x1 * gelu_tanh(x2);
    }
}

// ---------------------------------------------------------------------------
// Final readout
// ---------------------------------------------------------------------------
__global__ void k_final(const float* __restrict__ Smv, const float* __restrict__ Ss,
                        const float* __restrict__ wout_mv, const float* __restrict__ wout_sm,
                        float* __restrict__ out) {
    __shared__ float red[256];
    int b = blockIdx.x;
    float acc = 0.f;
    for (int n = threadIdx.x; n < NN; n += 256) {
        size_t t = (size_t)b*NN + n;
        float v = 0.f;
        #pragma unroll
        for (int i = 0; i < 16; i++) v = fmaf(__ldg(&wout_mv[i*9]), Smv[t*256 + i*16], v);
        #pragma unroll
        for (int j = 0; j < 32; j++) v = fmaf(__ldg(&wout_sm[j]), Ss[t*32 + j], v);
        acc += v;
    }
    red[threadIdx.x] = acc;
    __syncthreads();
    for (int s = 128; s; s >>= 1) {
        if (threadIdx.x < s) red[threadIdx.x] += red[threadIdx.x + s];
        __syncthreads();
    }
    if (threadIdx.x == 0) out[b] = red[0] * (1.f/NN);
}

// ---------------------------------------------------------------------------
// Host
// ---------------------------------------------------------------------------
template<int I, int O, int SI, int SO, bool RES, bool LN, bool QKV>
static void launch_equi(const float* xmv, const float* xs,
                        const float* wmv, const float* wsm,
                        const float* wms, const float* wss,
                        const float* rmv, const float* rs,
                        float* ymv, float* ys,
                        float* qc, float* kc, float* vc) {
    k_equi<I,O,SI,SO,RES,LN,QKV><<<NTOK/8, 256>>>(xmv, xs, wmv, wsm, wms, wss,
                                                  rmv, rs, ymv, ys, qc, kc, vc);
}

extern "C" void kernel_launch(void* const* d_in, const int* in_sizes, int n_in,
                              void* d_out, int out_size) {
    const float* inputs    = (const float*)d_in[0];
    const float* win_mv    = (const float*)d_in[1];
    const float* win_bs    = (const float*)d_in[3];
    const float* qkv_wmv   = (const float*)d_in[4];
    const float* qkv_wsm   = (const float*)d_in[5];
    const float* qkv_wms   = (const float*)d_in[6];
    const float* qkv_wss   = (const float*)d_in[7];
    const float* out_wmv   = (const float*)d_in[8];
    const float* out_wsm   = (const float*)d_in[9];
    const float* out_wms   = (const float*)d_in[10];
    const float* out_wss   = (const float*)d_in[11];
    const float* m1_wmv    = (const float*)d_in[12];
    const float* m1_wsm    = (const float*)d_in[13];
    const float* m1_wms    = (const float*)d_in[14];
    const float* m1_wss    = (const float*)d_in[15];
    const float* m2_wmv    = (const float*)d_in[16];
    const float* m2_wsm    = (const float*)d_in[17];
    const float* m2_wms    = (const float*)d_in[18];
    const float* m2_wss    = (const float*)d_in[19];
    const float* wout_mv   = (const float*)d_in[20];
    const float* wout_sm   = (const float*)d_in[21];
    float* out = (float*)d_out;

    int L = in_sizes[4] / (48*16*9);

    float *Smv, *Ss, *Qmv, *Qs, *Amv, *As, *Qc, *Kc, *Vc;
    cudaGetSymbolAddress((void**)&Smv, g_S_mv);
    cudaGetSymbolAddress((void**)&Ss,  g_S_s);
    cudaGetSymbolAddress((void**)&Qmv, g_Q_mv);
    cudaGetSymbolAddress((void**)&Qs,  g_Q_s);
    cudaGetSymbolAddress((void**)&Amv, g_A_mv);
    cudaGetSymbolAddress((void**)&As,  g_A_s);
    cudaGetSymbolAddress((void**)&Qc,  g_qc);
    cudaGetSymbolAddress((void**)&Kc,  g_kc);
    cudaGetSymbolAddress((void**)&Vc,  g_vc);

    k_init<<<NTOK/8, 256>>>(inputs, win_mv, win_bs, Smv, Ss);

    for (int l = 0; l < L; l++) {
        // --- attention block (LN fused into qkv equi; compact q/k/v out) ---
        launch_equi<16,48,32,96,false,true,true>(Smv, Ss,
            qkv_wmv + (size_t)l*48*16*9, qkv_wsm + (size_t)l*48*32,
            qkv_wms + (size_t)l*96*16,   qkv_wss + (size_t)l*96*32,
            nullptr, nullptr, nullptr, nullptr, Qc, Kc, Vc);
        k_attn<<<dim3(NN/64, BB*HH), 256>>>(Qc, Kc, Vc, Amv, As);
        launch_equi<16,16,32,32,true,false,false>(Amv, As,
            out_wmv + (size_t)l*16*16*9, out_wsm + (size_t)l*16*32,
            out_wms + (size_t)l*32*16,   out_wss + (size_t)l*32*32,
            Smv, Ss, Smv, Ss, nullptr, nullptr, nullptr);
        // --- mlp block (LN fused into mlp1 equi) ---
        launch_equi<16,32,32,64,false,true,false>(Smv, Ss,
            m1_wmv + (size_t)l*32*16*9, m1_wsm + (size_t)l*32*32,
            m1_wms + (size_t)l*64*16,   m1_wss + (size_t)l*64*32,
            nullptr, nullptr, Qmv, Qs, nullptr, nullptr, nullptr);
        k_geo<<<NTOK*16/256, 256>>>(Qmv, Qs, Amv, As);
        launch_equi<16,16,32,32,true,false,false>(Amv, As,
            m2_wmv + (size_t)l*16*16*9, m2_wsm + (size_t)l*16*32,
            m2_wms + (size_t)l*32*16,   m2_wss + (size_t)l*32*32,
            Smv, Ss, Smv, Ss, nullptr, nullptr, nullptr);
    }

    k_final<<<BB, 256>>>(Smv, Ss, wout_mv, wout_sm, out);
}